// round 2
// baseline (speedup 1.0000x reference)
#include <cuda_runtime.h>
#include <math.h>

#define BB 2
#define VV 3
#define CC 32
#define DD 32
#define HH 96
#define WW 128

#define NC 8            // channels per chunk
#define NCHUNK (CC / NC)
#define TH 8            // output rows per tile
#define THALO (TH + 2)
#define NTILE (HH / TH) // 12

// Scratch (static __device__ arrays; no allocation anywhere)
__device__ float g_RT[BB * VV * 12];                     // per (b,v): R(9), t(3)
__device__ float g_u[(size_t)BB * 3 * DD * HH * WW];     // (B, zz, D, H, W) ~9.4 MB

// ---------------------------------------------------------------------------
// Setup: per (b, src view v>=1): R = A_src * inv(A_ref), t = a_src - R*a_ref
// where composed = [A | a; 0 0 0 1], A = K3 @ E[:3,:3], a = K3 @ E[:3,3].
// ---------------------------------------------------------------------------
__global__ void k_setup(const float* __restrict__ proj) {
    int t = threadIdx.x;
    if (t >= BB * (VV - 1)) return;
    int b = t / (VV - 1);
    int v = 1 + t % (VV - 1);

    const float* Eref = proj + ((size_t)(b * VV + 0) * 2 + 0) * 16;
    const float* Kref = proj + ((size_t)(b * VV + 0) * 2 + 1) * 16;
    const float* Es   = proj + ((size_t)(b * VV + v) * 2 + 0) * 16;
    const float* Ks   = proj + ((size_t)(b * VV + v) * 2 + 1) * 16;

    float Ar[9], ar[3], As[9], asv[3];
    for (int i = 0; i < 3; i++) {
        for (int j = 0; j < 3; j++) {
            float s = 0.f, s2 = 0.f;
            for (int k = 0; k < 3; k++) {
                s  += Kref[i * 4 + k] * Eref[k * 4 + j];
                s2 += Ks[i * 4 + k]   * Es[k * 4 + j];
            }
            Ar[i * 3 + j] = s;
            As[i * 3 + j] = s2;
        }
        float s = 0.f, s2 = 0.f;
        for (int k = 0; k < 3; k++) {
            s  += Kref[i * 4 + k] * Eref[k * 4 + 3];
            s2 += Ks[i * 4 + k]   * Es[k * 4 + 3];
        }
        ar[i] = s;
        asv[i] = s2;
    }

    float det = Ar[0] * (Ar[4] * Ar[8] - Ar[5] * Ar[7])
              - Ar[1] * (Ar[3] * Ar[8] - Ar[5] * Ar[6])
              + Ar[2] * (Ar[3] * Ar[7] - Ar[4] * Ar[6]);
    float id = 1.0f / det;
    float Ai[9];
    Ai[0] = (Ar[4] * Ar[8] - Ar[5] * Ar[7]) * id;
    Ai[1] = (Ar[2] * Ar[7] - Ar[1] * Ar[8]) * id;
    Ai[2] = (Ar[1] * Ar[5] - Ar[2] * Ar[4]) * id;
    Ai[3] = (Ar[5] * Ar[6] - Ar[3] * Ar[8]) * id;
    Ai[4] = (Ar[0] * Ar[8] - Ar[2] * Ar[6]) * id;
    Ai[5] = (Ar[2] * Ar[3] - Ar[0] * Ar[5]) * id;
    Ai[6] = (Ar[3] * Ar[7] - Ar[4] * Ar[6]) * id;
    Ai[7] = (Ar[1] * Ar[6] - Ar[0] * Ar[7]) * id;
    Ai[8] = (Ar[0] * Ar[4] - Ar[1] * Ar[3]) * id;

    float R[9], tt[3];
    for (int i = 0; i < 3; i++)
        for (int j = 0; j < 3; j++) {
            float s = 0.f;
            for (int k = 0; k < 3; k++) s += As[i * 3 + k] * Ai[k * 3 + j];
            R[i * 3 + j] = s;
        }
    for (int i = 0; i < 3; i++) {
        float s = 0.f;
        for (int k = 0; k < 3; k++) s += R[i * 3 + k] * ar[k];
        tt[i] = asv[i] - s;
    }

    float* out = g_RT + (size_t)(b * VV + v) * 12;
    for (int i = 0; i < 9; i++) out[i] = R[i];
    for (int i = 0; i < 3; i++) out[9 + i] = tt[i];
}

// ---------------------------------------------------------------------------
// Fused kernel: warp + bilinear + variance -> smem tile -> 3-tap-split conv.
// CTA = (b, d, h-tile of TH rows). Channel chunked: NC ch/pass.
// Phase A: var for the (TH+2)-row haloed tile into smem.
// Phase B: accumulate u_zz (zz = depth tap) partial convs. Output (B,zz,D,H,W).
// ---------------------------------------------------------------------------
__global__ __launch_bounds__(256) void k_fused(const float* __restrict__ fea,
                                               const float* __restrict__ depthv,
                                               const float* __restrict__ wreg) {
    __shared__ float sv[NC][THALO][WW];   // 40 KB
    __shared__ float sh_w[27 * 32];       // [(zz*3+dy)*3+dx][c]

    const int tid = threadIdx.x;
    const int d  = blockIdx.x & (DD - 1);
    const int ht = (blockIdx.x >> 5) % NTILE;
    const int b  = blockIdx.x / (DD * NTILE);
    const int h0 = ht * TH;

    for (int i = tid; i < 864; i += 256) {
        int c = i / 27, r = i % 27;
        sh_w[r * 32 + c] = wreg[i];
    }

    // load homography params for this b (both source views) into registers
    float rt0[12], rt1[12];
    #pragma unroll
    for (int i = 0; i < 12; i++) {
        rt0[i] = g_RT[(size_t)(b * VV + 1) * 12 + i];
        rt1[i] = g_RT[(size_t)(b * VV + 2) * 12 + i];
    }

    const size_t plane = (size_t)HH * WW;
    const int rr = tid >> 5;            // output row within tile 0..7
    const int w0 = (tid & 31) * 4;      // output w group

    // accumulators: 3 depth taps x 4 w
    float a0x = 0.f, a0y = 0.f, a0z = 0.f, a0w = 0.f;
    float a1x = 0.f, a1y = 0.f, a1z = 0.f, a1w = 0.f;
    float a2x = 0.f, a2y = 0.f, a2z = 0.f, a2w = 0.f;

    for (int cg = 0; cg < NCHUNK; cg++) {
        const int c0 = cg * NC;
        __syncthreads();   // previous Phase B done before overwriting sv

        // ---------------- Phase A: variance into smem ----------------
        #pragma unroll
        for (int k = 0; k < (THALO * WW) / 256; k++) {
            int p = tid + k * 256;
            int hr = p >> 7;           // 0..THALO-1
            int w  = p & (WW - 1);
            int h  = h0 - 1 + hr;
            if ((unsigned)h >= (unsigned)HH) {
                #pragma unroll
                for (int c = 0; c < NC; c++) sv[c][hr][w] = 0.f;
                continue;
            }
            float dval = depthv[(((size_t)b * DD + d) * HH + h) * WW + w];

            int   cofs[2][4];
            float cw[2][4];
            #pragma unroll
            for (int vi = 0; vi < 2; vi++) {
                const float* rt = vi ? rt1 : rt0;
                float fw = (float)w, fh = (float)h;
                float X = (rt[0] * fw + rt[1] * fh + rt[2]) * dval + rt[9];
                float Y = (rt[3] * fw + rt[4] * fh + rt[5]) * dval + rt[10];
                float Z = (rt[6] * fw + rt[7] * fh + rt[8]) * dval + rt[11];
                float px = X / Z;
                float py = Y / Z;
                float x0f = floorf(px), y0f = floorf(py);
                float fx = px - x0f, fy = py - y0f;
                float wx[2] = {1.0f - fx, fx};
                float wy[2] = {1.0f - fy, fy};
                float xi[2] = {x0f, x0f + 1.0f};
                float yi[2] = {y0f, y0f + 1.0f};
                bool vx[2] = {xi[0] >= 0.0f && xi[0] <= (float)(WW - 1),
                              xi[1] >= 0.0f && xi[1] <= (float)(WW - 1)};
                bool vy[2] = {yi[0] >= 0.0f && yi[0] <= (float)(HH - 1),
                              yi[1] >= 0.0f && yi[1] <= (float)(HH - 1)};
                int xc[2] = {min(max((int)xi[0], 0), WW - 1), min(max((int)xi[1], 0), WW - 1)};
                int yc[2] = {min(max((int)yi[0], 0), HH - 1), min(max((int)yi[1], 0), HH - 1)};
                #pragma unroll
                for (int q = 0; q < 4; q++) {
                    int dx = q & 1, dy = q >> 1;
                    float wgt = wx[dx] * wy[dy];
                    if (!(vx[dx] && vy[dy])) wgt = 0.0f;
                    cw[vi][q] = wgt;
                    cofs[vi][q] = yc[dy] * WW + xc[dx];
                }
            }

            const float* feaRef = fea + ((size_t)(b * VV + 0) * CC + c0) * plane + (size_t)h * WW + w;
            const float* f0b    = fea + ((size_t)(b * VV + 1) * CC + c0) * plane;
            const float* f1b    = fea + ((size_t)(b * VV + 2) * CC + c0) * plane;

            #pragma unroll
            for (int c = 0; c < NC; c++) {
                size_t co = (size_t)c * plane;
                float r = feaRef[co];
                const float* f0 = f0b + co;
                const float* f1 = f1b + co;
                float wa0 = cw[0][0] * f0[cofs[0][0]] + cw[0][1] * f0[cofs[0][1]]
                          + cw[0][2] * f0[cofs[0][2]] + cw[0][3] * f0[cofs[0][3]];
                float wa1 = cw[1][0] * f1[cofs[1][0]] + cw[1][1] * f1[cofs[1][1]]
                          + cw[1][2] * f1[cofs[1][2]] + cw[1][3] * f1[cofs[1][3]];
                float s = r + wa0 + wa1;
                float q = r * r + wa0 * wa0 + wa1 * wa1;
                float sm = s * (1.0f / 3.0f);
                sv[c][hr][w] = q * (1.0f / 3.0f) - sm * sm;
            }
        }
        __syncthreads();

        // ---------------- Phase B: conv partial accumulation ----------------
        #pragma unroll
        for (int c = 0; c < NC; c++) {
            float wv[27];
            #pragma unroll
            for (int j = 0; j < 27; j++) wv[j] = sh_w[j * 32 + c0 + c];
            #pragma unroll
            for (int dy = 0; dy < 3; dy++) {
                const float* row = &sv[c][rr + dy][0];
                float xm = (w0 > 0) ? row[w0 - 1] : 0.0f;
                float4 v4 = *reinterpret_cast<const float4*>(row + w0);
                float xp = (w0 + 4 < WW) ? row[w0 + 4] : 0.0f;
                float x0 = xm, x1 = v4.x, x2 = v4.y, x3 = v4.z, x4 = v4.w, x5 = xp;

                float wA, wB, wC;
                wA = wv[(0 * 3 + dy) * 3 + 0]; wB = wv[(0 * 3 + dy) * 3 + 1]; wC = wv[(0 * 3 + dy) * 3 + 2];
                a0x += wA * x0 + wB * x1 + wC * x2;
                a0y += wA * x1 + wB * x2 + wC * x3;
                a0z += wA * x2 + wB * x3 + wC * x4;
                a0w += wA * x3 + wB * x4 + wC * x5;
                wA = wv[(1 * 3 + dy) * 3 + 0]; wB = wv[(1 * 3 + dy) * 3 + 1]; wC = wv[(1 * 3 + dy) * 3 + 2];
                a1x += wA * x0 + wB * x1 + wC * x2;
                a1y += wA * x1 + wB * x2 + wC * x3;
                a1z += wA * x2 + wB * x3 + wC * x4;
                a1w += wA * x3 + wB * x4 + wC * x5;
                wA = wv[(2 * 3 + dy) * 3 + 0]; wB = wv[(2 * 3 + dy) * 3 + 1]; wC = wv[(2 * 3 + dy) * 3 + 2];
                a2x += wA * x0 + wB * x1 + wC * x2;
                a2y += wA * x1 + wB * x2 + wC * x3;
                a2z += wA * x2 + wB * x3 + wC * x4;
                a2w += wA * x3 + wB * x4 + wC * x5;
            }
        }
    }

    size_t obase = (((size_t)b * 3 + 0) * DD + d) * plane + (size_t)(h0 + rr) * WW + w0;
    size_t zstep = (size_t)DD * plane;
    *reinterpret_cast<float4*>(g_u + obase)             = make_float4(a0x, a0y, a0z, a0w);
    *reinterpret_cast<float4*>(g_u + obase + zstep)     = make_float4(a1x, a1y, a1z, a1w);
    *reinterpret_cast<float4*>(g_u + obase + 2 * zstep) = make_float4(a2x, a2y, a2z, a2w);
}

// ---------------------------------------------------------------------------
// Final: pre[d] = u0[d-1] + u1[d] + u2[d+1]; softmax over D; expected depth;
// confidence = sum p[idx-1..idx+2]. One block per (b,h) row; stage u in smem.
// ---------------------------------------------------------------------------
__global__ __launch_bounds__(128) void k_final(const float* __restrict__ depthv,
                                               float* __restrict__ out) {
    __shared__ float su[3][DD][WW];   // 48 KB

    const int tid = threadIdx.x;
    const int h = blockIdx.x % HH;
    const int b = blockIdx.x / HH;
    const size_t plane = (size_t)HH * WW;

    // cooperative stage: 3*32*32 float4 groups
    #pragma unroll
    for (int i = tid; i < 3 * DD * (WW / 4); i += 128) {
        int zz = i / (DD * (WW / 4));
        int dd = (i / (WW / 4)) % DD;
        int j  = i % (WW / 4);
        const float* src = g_u + (((size_t)b * 3 + zz) * DD + dd) * plane + (size_t)h * WW + j * 4;
        float4 v = *reinterpret_cast<const float4*>(src);
        *reinterpret_cast<float4*>(&su[zz][dd][j * 4]) = v;
    }
    __syncthreads();

    const int w = tid;   // 128 threads = 128 w
    float pre[DD];
    #pragma unroll
    for (int d = 0; d < DD; d++) {
        float v = su[1][d][w];
        if (d > 0)      v += su[0][d - 1][w];
        if (d < DD - 1) v += su[2][d + 1][w];
        pre[d] = v;
    }

    float m = pre[0];
    #pragma unroll
    for (int d = 1; d < DD; d++) m = fmaxf(m, pre[d]);

    float s = 0.f;
    #pragma unroll
    for (int d = 0; d < DD; d++) {
        float e = __expf(pre[d] - m);
        pre[d] = e;
        s += e;
    }
    float inv = 1.0f / s;

    const float* dv = depthv + (size_t)b * DD * plane + (size_t)h * WW + w;
    float depth = 0.f, sidx = 0.f;
    #pragma unroll
    for (int d = 0; d < DD; d++) {
        float p = pre[d] * inv;
        pre[d] = p;
        depth += p * dv[(size_t)d * plane];
        sidx  += p * (float)d;
    }

    int idx = (int)sidx;
    if (idx < 0) idx = 0;
    if (idx > DD - 1) idx = DD - 1;

    float conf = 0.f;
    #pragma unroll
    for (int d = 0; d < DD; d++) {
        if (d >= idx - 1 && d <= idx + 2) conf += pre[d];
    }

    int gid = (b * HH + h) * WW + w;
    out[gid] = depth;
    out[BB * HH * WW + gid] = conf;
}

// ---------------------------------------------------------------------------
extern "C" void kernel_launch(void* const* d_in, const int* in_sizes, int n_in,
                              void* d_out, int out_size) {
    const float* features = (const float*)d_in[0];   // (B,V,C,H,W)
    const float* proj     = (const float*)d_in[1];   // (B,V,2,4,4)
    const float* depthv   = (const float*)d_in[2];   // (B,D,H,W)
    const float* wreg     = (const float*)d_in[3];   // (1,C,3,3,3)
    // d_in[4] = b_reg: cancels in softmax, unused
    float* out = (float*)d_out;

    k_setup<<<1, 32>>>(proj);
    k_fused<<<BB * NTILE * DD, 256>>>(features, depthv, wreg);
    k_final<<<BB * HH, 128>>>(depthv, out);
}

// round 3
// speedup vs baseline: 1.1240x; 1.1240x over previous
#include <cuda_runtime.h>
#include <math.h>

#define BB 2
#define VV 3
#define CC 32
#define DD 32
#define HH 96
#define WW 128

// Scratch (static __device__ arrays; no allocation anywhere)
__device__ float g_var[(size_t)BB * DD * CC * HH * WW];      // (B, D, C, H, W)  ~100.7 MB
__device__ float g_u[(size_t)BB * 3 * DD * HH * WW];         // (B, zz, D, H, W) ~9.4 MB

// ---------------------------------------------------------------------------
// In-block projection setup: R = A_src * inv(A_ref), t = a_src - R*a_ref
// A = K3 @ E[:3,:3], a = K3 @ E[:3,3].  Result -> s_rt[v-1][0..11] (R, t)
// ---------------------------------------------------------------------------
__device__ __forceinline__ void compute_rt(const float* __restrict__ proj,
                                           int b, int v, float* __restrict__ out) {
    const float* Eref = proj + ((size_t)(b * VV + 0) * 2 + 0) * 16;
    const float* Kref = proj + ((size_t)(b * VV + 0) * 2 + 1) * 16;
    const float* Es   = proj + ((size_t)(b * VV + v) * 2 + 0) * 16;
    const float* Ks   = proj + ((size_t)(b * VV + v) * 2 + 1) * 16;

    float Ar[9], ar[3], As[9], asv[3];
    for (int i = 0; i < 3; i++) {
        for (int j = 0; j < 3; j++) {
            float s = 0.f, s2 = 0.f;
            for (int k = 0; k < 3; k++) {
                s  += Kref[i * 4 + k] * Eref[k * 4 + j];
                s2 += Ks[i * 4 + k]   * Es[k * 4 + j];
            }
            Ar[i * 3 + j] = s;
            As[i * 3 + j] = s2;
        }
        float s = 0.f, s2 = 0.f;
        for (int k = 0; k < 3; k++) {
            s  += Kref[i * 4 + k] * Eref[k * 4 + 3];
            s2 += Ks[i * 4 + k]   * Es[k * 4 + 3];
        }
        ar[i] = s;
        asv[i] = s2;
    }

    float det = Ar[0] * (Ar[4] * Ar[8] - Ar[5] * Ar[7])
              - Ar[1] * (Ar[3] * Ar[8] - Ar[5] * Ar[6])
              + Ar[2] * (Ar[3] * Ar[7] - Ar[4] * Ar[6]);
    float id = 1.0f / det;
    float Ai[9];
    Ai[0] = (Ar[4] * Ar[8] - Ar[5] * Ar[7]) * id;
    Ai[1] = (Ar[2] * Ar[7] - Ar[1] * Ar[8]) * id;
    Ai[2] = (Ar[1] * Ar[5] - Ar[2] * Ar[4]) * id;
    Ai[3] = (Ar[5] * Ar[6] - Ar[3] * Ar[8]) * id;
    Ai[4] = (Ar[0] * Ar[8] - Ar[2] * Ar[6]) * id;
    Ai[5] = (Ar[2] * Ar[3] - Ar[0] * Ar[5]) * id;
    Ai[6] = (Ar[3] * Ar[7] - Ar[4] * Ar[6]) * id;
    Ai[7] = (Ar[1] * Ar[6] - Ar[0] * Ar[7]) * id;
    Ai[8] = (Ar[0] * Ar[4] - Ar[1] * Ar[3]) * id;

    float R[9], tt[3];
    for (int i = 0; i < 3; i++)
        for (int j = 0; j < 3; j++) {
            float s = 0.f;
            for (int k = 0; k < 3; k++) s += As[i * 3 + k] * Ai[k * 3 + j];
            R[i * 3 + j] = s;
        }
    for (int i = 0; i < 3; i++) {
        float s = 0.f;
        for (int k = 0; k < 3; k++) s += R[i * 3 + k] * ar[k];
        tt[i] = asv[i] - s;
    }
    for (int i = 0; i < 9; i++) out[i] = R[i];
    for (int i = 0; i < 3; i++) out[9 + i] = tt[i];
}

// ---------------------------------------------------------------------------
// Kernel 1: homography warp + bilinear + running variance over 3 views.
// One thread per (b,d,h,w); lanes map to w -> coalesced fea reads & var writes.
// var layout: (B, D, C, H, W).
// ---------------------------------------------------------------------------
__global__ __launch_bounds__(256) void k_warpvar(const float* __restrict__ fea,
                                                 const float* __restrict__ proj,
                                                 const float* __restrict__ depthv) {
    __shared__ float s_rt[2][12];

    int tid = blockIdx.x * blockDim.x + threadIdx.x;   // exact grid: B*D*H*W
    int b = tid / (WW * HH * DD);

    if (threadIdx.x < 2)
        compute_rt(proj, b, threadIdx.x + 1, s_rt[threadIdx.x]);
    __syncthreads();

    int w = tid & (WW - 1);
    int h = (tid / WW) % HH;
    int d = (tid / (WW * HH)) % DD;

    float dval = depthv[tid];   // depth_values has the same (B,D,H,W) layout

    int   cofs[2][4];
    float cw[2][4];
    #pragma unroll
    for (int vi = 0; vi < 2; vi++) {
        const float* rt = s_rt[vi];
        float fw = (float)w, fh = (float)h;
        float X = (rt[0] * fw + rt[1] * fh + rt[2]) * dval + rt[9];
        float Y = (rt[3] * fw + rt[4] * fh + rt[5]) * dval + rt[10];
        float Z = (rt[6] * fw + rt[7] * fh + rt[8]) * dval + rt[11];
        float px = X / Z;
        float py = Y / Z;
        float x0f = floorf(px), y0f = floorf(py);
        float fx = px - x0f, fy = py - y0f;
        float wx[2] = {1.0f - fx, fx};
        float wy[2] = {1.0f - fy, fy};
        float xi[2] = {x0f, x0f + 1.0f};
        float yi[2] = {y0f, y0f + 1.0f};
        bool vx[2] = {xi[0] >= 0.0f && xi[0] <= (float)(WW - 1),
                      xi[1] >= 0.0f && xi[1] <= (float)(WW - 1)};
        bool vy[2] = {yi[0] >= 0.0f && yi[0] <= (float)(HH - 1),
                      yi[1] >= 0.0f && yi[1] <= (float)(HH - 1)};
        int xc[2] = {min(max((int)xi[0], 0), WW - 1), min(max((int)xi[1], 0), WW - 1)};
        int yc[2] = {min(max((int)yi[0], 0), HH - 1), min(max((int)yi[1], 0), HH - 1)};
        #pragma unroll
        for (int k = 0; k < 4; k++) {
            int dx = k & 1, dy = k >> 1;
            float wgt = wx[dx] * wy[dy];
            if (!(vx[dx] && vy[dy])) wgt = 0.0f;
            cw[vi][k] = wgt;
            cofs[vi][k] = yc[dy] * WW + xc[dx];
        }
    }

    const size_t plane = (size_t)HH * WW;
    const float* feaRef = fea + (size_t)(b * VV + 0) * CC * plane + (size_t)h * WW + w;
    const float* feaS0  = fea + (size_t)(b * VV + 1) * CC * plane;
    const float* feaS1  = fea + (size_t)(b * VV + 2) * CC * plane;
    float* varBase = g_var + (size_t)(b * DD + d) * CC * plane + (size_t)h * WW + w;

    #pragma unroll 8
    for (int c = 0; c < CC; c++) {
        size_t co = (size_t)c * plane;
        float r = feaRef[co];
        float s = r, q = r * r;

        const float* f0 = feaS0 + co;
        float wa0 = cw[0][0] * f0[cofs[0][0]] + cw[0][1] * f0[cofs[0][1]]
                  + cw[0][2] * f0[cofs[0][2]] + cw[0][3] * f0[cofs[0][3]];
        s += wa0; q += wa0 * wa0;

        const float* f1 = feaS1 + co;
        float wa1 = cw[1][0] * f1[cofs[1][0]] + cw[1][1] * f1[cofs[1][1]]
                  + cw[1][2] * f1[cofs[1][2]] + cw[1][3] * f1[cofs[1][3]];
        s += wa1; q += wa1 * wa1;

        float sm = s * (1.0f / 3.0f);
        varBase[co] = q * (1.0f / 3.0f) - sm * sm;
    }
}

// ---------------------------------------------------------------------------
// Packed f32x2 helpers
// ---------------------------------------------------------------------------
__device__ __forceinline__ unsigned long long pack2(float lo, float hi) {
    unsigned long long r;
    asm("mov.b64 %0, {%1, %2};" : "=l"(r) : "f"(lo), "f"(hi));
    return r;
}
__device__ __forceinline__ void fma2(unsigned long long& acc,
                                     unsigned long long a, unsigned long long b) {
    asm("fma.rn.f32x2 %0, %1, %2, %0;" : "+l"(acc) : "l"(a), "l"(b));
}
__device__ __forceinline__ float2 unpack2(unsigned long long v) {
    float lo, hi;
    asm("mov.b64 {%0, %1}, %2;" : "=f"(lo), "=f"(hi) : "l"(v));
    return make_float2(lo, hi);
}

// ---------------------------------------------------------------------------
// Kernel 2: per var slice dd, the three depth-tap partial 2D convs via FFMA2:
//   u_zz(b,dd,h,w) = sum_{c,dy,dx} w_reg[c,zz,dy,dx] * var[b,dd,c,h+dy-1,w+dx-1]
// Each thread produces 4 consecutive-w outputs, packed as 2 f32x2 pairs.
// Weight pairs pre-duplicated in smem (LDS.64 broadcast, no pack cost).
// ---------------------------------------------------------------------------
__global__ __launch_bounds__(128) void k_conv_u(const float* __restrict__ wreg) {
    __shared__ unsigned long long sh_w2[27 * 32];   // [ (zz*3+dy)*3+dx ][ c ], dup pairs
    int tid = threadIdx.x;
    for (int i = tid; i < 864; i += blockDim.x) {
        int c = i / 27, r = i % 27;
        unsigned int u = __float_as_uint(wreg[i]);
        sh_w2[r * 32 + c] = ((unsigned long long)u << 32) | (unsigned long long)u;
    }
    __syncthreads();

    int gid = blockIdx.x * blockDim.x + tid;   // exact grid: B*D*H*(W/4)
    int wi = gid & 31;
    int w0 = wi * 4;
    int rest = gid >> 5;
    int h  = rest % HH;
    int dd = (rest / HH) % DD;
    int b  = rest / (HH * DD);

    unsigned long long u0ab = 0ull, u0cd = 0ull;
    unsigned long long u1ab = 0ull, u1cd = 0ull;
    unsigned long long u2ab = 0ull, u2cd = 0ull;

    const size_t plane = (size_t)HH * WW;
    const float* sbase = g_var + (size_t)(b * DD + dd) * CC * plane;

    #pragma unroll
    for (int dy = 0; dy < 3; dy++) {
        int hy = h + dy - 1;
        if ((unsigned)hy >= (unsigned)HH) continue;
        #pragma unroll 4
        for (int c = 0; c < CC; c++) {
            const float* row = sbase + (size_t)c * plane + (size_t)hy * WW;
            float xm = (w0 > 0) ? row[w0 - 1] : 0.0f;
            float4 v4 = *reinterpret_cast<const float4*>(row + w0);
            float xp = (w0 + 4 < WW) ? row[w0 + 4] : 0.0f;

            unsigned long long p01 = pack2(xm,   v4.x);
            unsigned long long p12 = pack2(v4.x, v4.y);
            unsigned long long p23 = pack2(v4.y, v4.z);
            unsigned long long p34 = pack2(v4.z, v4.w);
            unsigned long long p45 = pack2(v4.w, xp);

            const unsigned long long* wrow = sh_w2 + c;
            {
                unsigned long long wA = wrow[((0 * 3 + dy) * 3 + 0) * 32];
                unsigned long long wB = wrow[((0 * 3 + dy) * 3 + 1) * 32];
                unsigned long long wC = wrow[((0 * 3 + dy) * 3 + 2) * 32];
                fma2(u0ab, wA, p01); fma2(u0ab, wB, p12); fma2(u0ab, wC, p23);
                fma2(u0cd, wA, p23); fma2(u0cd, wB, p34); fma2(u0cd, wC, p45);
            }
            {
                unsigned long long wA = wrow[((1 * 3 + dy) * 3 + 0) * 32];
                unsigned long long wB = wrow[((1 * 3 + dy) * 3 + 1) * 32];
                unsigned long long wC = wrow[((1 * 3 + dy) * 3 + 2) * 32];
                fma2(u1ab, wA, p01); fma2(u1ab, wB, p12); fma2(u1ab, wC, p23);
                fma2(u1cd, wA, p23); fma2(u1cd, wB, p34); fma2(u1cd, wC, p45);
            }
            {
                unsigned long long wA = wrow[((2 * 3 + dy) * 3 + 0) * 32];
                unsigned long long wB = wrow[((2 * 3 + dy) * 3 + 1) * 32];
                unsigned long long wC = wrow[((2 * 3 + dy) * 3 + 2) * 32];
                fma2(u2ab, wA, p01); fma2(u2ab, wB, p12); fma2(u2ab, wC, p23);
                fma2(u2cd, wA, p23); fma2(u2cd, wB, p34); fma2(u2cd, wC, p45);
            }
        }
    }

    float2 r0ab = unpack2(u0ab), r0cd = unpack2(u0cd);
    float2 r1ab = unpack2(u1ab), r1cd = unpack2(u1cd);
    float2 r2ab = unpack2(u2ab), r2cd = unpack2(u2cd);

    size_t obase = (((size_t)b * 3 + 0) * DD + dd) * plane + (size_t)h * WW + w0;
    size_t zstep = (size_t)DD * plane;
    *reinterpret_cast<float4*>(g_u + obase)             = make_float4(r0ab.x, r0ab.y, r0cd.x, r0cd.y);
    *reinterpret_cast<float4*>(g_u + obase + zstep)     = make_float4(r1ab.x, r1ab.y, r1cd.x, r1cd.y);
    *reinterpret_cast<float4*>(g_u + obase + 2 * zstep) = make_float4(r2ab.x, r2ab.y, r2cd.x, r2cd.y);
}

// ---------------------------------------------------------------------------
// Kernel 3: pre[d] = u0[d-1] + u1[d] + u2[d+1]; softmax over D; expected depth;
// confidence = sum p[idx-1..idx+2]. One block per (b,h) row; stage u in smem.
// ---------------------------------------------------------------------------
__global__ __launch_bounds__(128) void k_final(const float* __restrict__ depthv,
                                               float* __restrict__ out) {
    __shared__ float su[3][DD][WW];   // 48 KB

    const int tid = threadIdx.x;
    const int h = blockIdx.x % HH;
    const int b = blockIdx.x / HH;
    const size_t plane = (size_t)HH * WW;

    #pragma unroll
    for (int i = tid; i < 3 * DD * (WW / 4); i += 128) {
        int zz = i / (DD * (WW / 4));
        int dd = (i / (WW / 4)) % DD;
        int j  = i % (WW / 4);
        const float* src = g_u + (((size_t)b * 3 + zz) * DD + dd) * plane + (size_t)h * WW + j * 4;
        float4 v = *reinterpret_cast<const float4*>(src);
        *reinterpret_cast<float4*>(&su[zz][dd][j * 4]) = v;
    }
    __syncthreads();

    const int w = tid;   // 128 threads = 128 w
    float pre[DD];
    #pragma unroll
    for (int d = 0; d < DD; d++) {
        float v = su[1][d][w];
        if (d > 0)      v += su[0][d - 1][w];
        if (d < DD - 1) v += su[2][d + 1][w];
        pre[d] = v;
    }

    float m = pre[0];
    #pragma unroll
    for (int d = 1; d < DD; d++) m = fmaxf(m, pre[d]);

    float s = 0.f;
    #pragma unroll
    for (int d = 0; d < DD; d++) {
        float e = __expf(pre[d] - m);
        pre[d] = e;
        s += e;
    }
    float inv = 1.0f / s;

    const float* dv = depthv + (size_t)b * DD * plane + (size_t)h * WW + w;
    float depth = 0.f, sidx = 0.f;
    #pragma unroll
    for (int d = 0; d < DD; d++) {
        float p = pre[d] * inv;
        pre[d] = p;
        depth += p * dv[(size_t)d * plane];
        sidx  += p * (float)d;
    }

    int idx = (int)sidx;
    if (idx < 0) idx = 0;
    if (idx > DD - 1) idx = DD - 1;

    float conf = 0.f;
    #pragma unroll
    for (int d = 0; d < DD; d++) {
        if (d >= idx - 1 && d <= idx + 2) conf += pre[d];
    }

    int gid = (b * HH + h) * WW + w;
    out[gid] = depth;
    out[BB * HH * WW + gid] = conf;
}

// ---------------------------------------------------------------------------
extern "C" void kernel_launch(void* const* d_in, const int* in_sizes, int n_in,
                              void* d_out, int out_size) {
    const float* features = (const float*)d_in[0];   // (B,V,C,H,W)
    const float* proj     = (const float*)d_in[1];   // (B,V,2,4,4)
    const float* depthv   = (const float*)d_in[2];   // (B,D,H,W)
    const float* wreg     = (const float*)d_in[3];   // (1,C,3,3,3)
    // d_in[4] = b_reg: cancels in softmax, unused
    float* out = (float*)d_out;

    k_warpvar<<<(BB * DD * HH * WW) / 256, 256>>>(features, proj, depthv);
    k_conv_u<<<(BB * DD * HH * (WW / 4)) / 128, 128>>>(wreg);
    k_final<<<BB * HH, 128>>>(depthv, out);
}

// round 4
// speedup vs baseline: 1.1359x; 1.0106x over previous
#include <cuda_runtime.h>
#include <math.h>

#define BB 2
#define VV 3
#define CC 32
#define DD 32
#define HH 96
#define WW 128

#define NC 4            // channels per chunk
#define NCHUNK (CC / NC)
#define TH 8            // output rows per tile
#define THALO (TH + 2)
#define NTILE (HH / TH) // 12

__device__ float g_u[(size_t)BB * 3 * DD * HH * WW];     // (B, zz, D, H, W) ~9.4 MB

// ---------------------------------------------------------------------------
// Packed f32x2 helpers
// ---------------------------------------------------------------------------
__device__ __forceinline__ unsigned long long pack2(float lo, float hi) {
    unsigned long long r;
    asm("mov.b64 %0, {%1, %2};" : "=l"(r) : "f"(lo), "f"(hi));
    return r;
}
__device__ __forceinline__ void fma2(unsigned long long& acc,
                                     unsigned long long a, unsigned long long b) {
    asm("fma.rn.f32x2 %0, %1, %2, %0;" : "+l"(acc) : "l"(a), "l"(b));
}
__device__ __forceinline__ float2 unpack2(unsigned long long v) {
    float lo, hi;
    asm("mov.b64 {%0, %1}, %2;" : "=f"(lo), "=f"(hi) : "l"(v));
    return make_float2(lo, hi);
}

// ---------------------------------------------------------------------------
// In-block projection setup: R = A_src * inv(A_ref), t = a_src - R*a_ref
// A = K3 @ E[:3,:3], a = K3 @ E[:3,3].
// ---------------------------------------------------------------------------
__device__ __forceinline__ void compute_rt(const float* __restrict__ proj,
                                           int b, int v, float* __restrict__ out) {
    const float* Eref = proj + ((size_t)(b * VV + 0) * 2 + 0) * 16;
    const float* Kref = proj + ((size_t)(b * VV + 0) * 2 + 1) * 16;
    const float* Es   = proj + ((size_t)(b * VV + v) * 2 + 0) * 16;
    const float* Ks   = proj + ((size_t)(b * VV + v) * 2 + 1) * 16;

    float Ar[9], ar[3], As[9], asv[3];
    for (int i = 0; i < 3; i++) {
        for (int j = 0; j < 3; j++) {
            float s = 0.f, s2 = 0.f;
            for (int k = 0; k < 3; k++) {
                s  += Kref[i * 4 + k] * Eref[k * 4 + j];
                s2 += Ks[i * 4 + k]   * Es[k * 4 + j];
            }
            Ar[i * 3 + j] = s;
            As[i * 3 + j] = s2;
        }
        float s = 0.f, s2 = 0.f;
        for (int k = 0; k < 3; k++) {
            s  += Kref[i * 4 + k] * Eref[k * 4 + 3];
            s2 += Ks[i * 4 + k]   * Es[k * 4 + 3];
        }
        ar[i] = s;
        asv[i] = s2;
    }

    float det = Ar[0] * (Ar[4] * Ar[8] - Ar[5] * Ar[7])
              - Ar[1] * (Ar[3] * Ar[8] - Ar[5] * Ar[6])
              + Ar[2] * (Ar[3] * Ar[7] - Ar[4] * Ar[6]);
    float id = 1.0f / det;
    float Ai[9];
    Ai[0] = (Ar[4] * Ar[8] - Ar[5] * Ar[7]) * id;
    Ai[1] = (Ar[2] * Ar[7] - Ar[1] * Ar[8]) * id;
    Ai[2] = (Ar[1] * Ar[5] - Ar[2] * Ar[4]) * id;
    Ai[3] = (Ar[5] * Ar[6] - Ar[3] * Ar[8]) * id;
    Ai[4] = (Ar[0] * Ar[8] - Ar[2] * Ar[6]) * id;
    Ai[5] = (Ar[2] * Ar[3] - Ar[0] * Ar[5]) * id;
    Ai[6] = (Ar[3] * Ar[7] - Ar[4] * Ar[6]) * id;
    Ai[7] = (Ar[1] * Ar[6] - Ar[0] * Ar[7]) * id;
    Ai[8] = (Ar[0] * Ar[4] - Ar[1] * Ar[3]) * id;

    float R[9], tt[3];
    for (int i = 0; i < 3; i++)
        for (int j = 0; j < 3; j++) {
            float s = 0.f;
            for (int k = 0; k < 3; k++) s += As[i * 3 + k] * Ai[k * 3 + j];
            R[i * 3 + j] = s;
        }
    for (int i = 0; i < 3; i++) {
        float s = 0.f;
        for (int k = 0; k < 3; k++) s += R[i * 3 + k] * ar[k];
        tt[i] = asv[i] - s;
    }
    for (int i = 0; i < 9; i++) out[i] = R[i];
    for (int i = 0; i < 3; i++) out[9 + i] = tt[i];
}

// ---------------------------------------------------------------------------
// Fused kernel: warp + bilinear + variance -> smem tile -> 3-tap-split conv.
// CTA = (b, d, 8-row h-tile). Geometry (px,py per view) computed ONCE into
// smem; per channel-chunk only the cheap corner weights are re-derived.
// ---------------------------------------------------------------------------
__global__ __launch_bounds__(256) void k_fused(const float* __restrict__ fea,
                                               const float* __restrict__ proj,
                                               const float* __restrict__ depthv,
                                               const float* __restrict__ wreg) {
    __shared__ float4 sg[THALO * WW];               // 20 KB: px0,py0,px1,py1
    __shared__ float sv[NC][THALO][WW];             // 20 KB
    __shared__ unsigned long long sh_w2[27 * 32];   // 6.9 KB, dup weight pairs
    __shared__ float s_rt[2][12];

    const int tid = threadIdx.x;
    const int d  = blockIdx.x & (DD - 1);
    const int ht = (blockIdx.x >> 5) % NTILE;
    const int b  = blockIdx.x / (DD * NTILE);
    const int h0 = ht * TH;

    if (tid < 2) compute_rt(proj, b, tid + 1, s_rt[tid]);
    for (int i = tid; i < 864; i += 256) {
        int c = i / 27, r = i % 27;
        unsigned int u = __float_as_uint(wreg[i]);
        sh_w2[r * 32 + c] = ((unsigned long long)u << 32) | (unsigned long long)u;
    }
    __syncthreads();

    // ---- geometry: once per CTA ----
    #pragma unroll
    for (int k = 0; k < (THALO * WW) / 256; k++) {
        int p = tid + k * 256;
        int hr = p >> 7;
        int w  = p & (WW - 1);
        int h  = h0 - 1 + hr;
        if ((unsigned)h < (unsigned)HH) {
            float dval = depthv[(((size_t)b * DD + d) * HH + h) * WW + w];
            float fw = (float)w, fh = (float)h;
            float4 g;
            {
                const float* rt = s_rt[0];
                float X = (rt[0] * fw + rt[1] * fh + rt[2]) * dval + rt[9];
                float Y = (rt[3] * fw + rt[4] * fh + rt[5]) * dval + rt[10];
                float Z = (rt[6] * fw + rt[7] * fh + rt[8]) * dval + rt[11];
                float iz = __fdividef(1.0f, Z);
                g.x = X * iz; g.y = Y * iz;
            }
            {
                const float* rt = s_rt[1];
                float X = (rt[0] * fw + rt[1] * fh + rt[2]) * dval + rt[9];
                float Y = (rt[3] * fw + rt[4] * fh + rt[5]) * dval + rt[10];
                float Z = (rt[6] * fw + rt[7] * fh + rt[8]) * dval + rt[11];
                float iz = __fdividef(1.0f, Z);
                g.z = X * iz; g.w = Y * iz;
            }
            sg[p] = g;
        }
    }
    __syncthreads();

    const size_t plane = (size_t)HH * WW;
    const int rr = tid >> 5;            // output row within tile 0..7
    const int w0 = (tid & 31) * 4;      // output w group

    unsigned long long u0ab = 0ull, u0cd = 0ull;
    unsigned long long u1ab = 0ull, u1cd = 0ull;
    unsigned long long u2ab = 0ull, u2cd = 0ull;

    for (int cg = 0; cg < NCHUNK; cg++) {
        const int c0 = cg * NC;
        if (cg) __syncthreads();   // previous phase B done before overwriting sv

        // ---------------- Phase A: variance into smem ----------------
        #pragma unroll
        for (int k = 0; k < (THALO * WW) / 256; k++) {
            int p = tid + k * 256;
            int hr = p >> 7;
            int w  = p & (WW - 1);
            int h  = h0 - 1 + hr;
            if ((unsigned)h >= (unsigned)HH) {
                #pragma unroll
                for (int c = 0; c < NC; c++) sv[c][hr][w] = 0.f;
                continue;
            }
            float4 g = sg[p];

            int   cofs[2][4];
            float cw[2][4];
            #pragma unroll
            for (int vi = 0; vi < 2; vi++) {
                float px = vi ? g.z : g.x;
                float py = vi ? g.w : g.y;
                float x0f = floorf(px), y0f = floorf(py);
                float fx = px - x0f, fy = py - y0f;
                float wx[2] = {1.0f - fx, fx};
                float wy[2] = {1.0f - fy, fy};
                float xi[2] = {x0f, x0f + 1.0f};
                float yi[2] = {y0f, y0f + 1.0f};
                bool vx[2] = {xi[0] >= 0.0f && xi[0] <= (float)(WW - 1),
                              xi[1] >= 0.0f && xi[1] <= (float)(WW - 1)};
                bool vy[2] = {yi[0] >= 0.0f && yi[0] <= (float)(HH - 1),
                              yi[1] >= 0.0f && yi[1] <= (float)(HH - 1)};
                int xc[2] = {min(max((int)xi[0], 0), WW - 1), min(max((int)xi[1], 0), WW - 1)};
                int yc[2] = {min(max((int)yi[0], 0), HH - 1), min(max((int)yi[1], 0), HH - 1)};
                #pragma unroll
                for (int q = 0; q < 4; q++) {
                    int dx = q & 1, dyq = q >> 1;
                    float wgt = wx[dx] * wy[dyq];
                    if (!(vx[dx] && vy[dyq])) wgt = 0.0f;
                    cw[vi][q] = wgt;
                    cofs[vi][q] = yc[dyq] * WW + xc[dx];
                }
            }

            const float* feaRef = fea + ((size_t)(b * VV + 0) * CC + c0) * plane + (size_t)h * WW + w;
            const float* f0b    = fea + ((size_t)(b * VV + 1) * CC + c0) * plane;
            const float* f1b    = fea + ((size_t)(b * VV + 2) * CC + c0) * plane;

            #pragma unroll
            for (int c = 0; c < NC; c++) {
                size_t co = (size_t)c * plane;
                float r = feaRef[co];
                const float* f0 = f0b + co;
                const float* f1 = f1b + co;
                float wa0 = cw[0][0] * f0[cofs[0][0]] + cw[0][1] * f0[cofs[0][1]]
                          + cw[0][2] * f0[cofs[0][2]] + cw[0][3] * f0[cofs[0][3]];
                float wa1 = cw[1][0] * f1[cofs[1][0]] + cw[1][1] * f1[cofs[1][1]]
                          + cw[1][2] * f1[cofs[1][2]] + cw[1][3] * f1[cofs[1][3]];
                float s = r + wa0 + wa1;
                float q = r * r + wa0 * wa0 + wa1 * wa1;
                float sm = s * (1.0f / 3.0f);
                sv[c][hr][w] = q * (1.0f / 3.0f) - sm * sm;
            }
        }
        __syncthreads();

        // ---------------- Phase B: packed FFMA2 conv accumulation ----------------
        #pragma unroll
        for (int c = 0; c < NC; c++) {
            const unsigned long long* wrow = sh_w2 + (c0 + c);
            #pragma unroll
            for (int dy = 0; dy < 3; dy++) {
                const float* row = &sv[c][rr + dy][0];
                float xm = (w0 > 0) ? row[w0 - 1] : 0.0f;
                float4 v4 = *reinterpret_cast<const float4*>(row + w0);
                float xp = (w0 + 4 < WW) ? row[w0 + 4] : 0.0f;

                unsigned long long p01 = pack2(xm,   v4.x);
                unsigned long long p12 = pack2(v4.x, v4.y);
                unsigned long long p23 = pack2(v4.y, v4.z);
                unsigned long long p34 = pack2(v4.z, v4.w);
                unsigned long long p45 = pack2(v4.w, xp);

                {
                    unsigned long long wA = wrow[((0 * 3 + dy) * 3 + 0) * 32];
                    unsigned long long wB = wrow[((0 * 3 + dy) * 3 + 1) * 32];
                    unsigned long long wC = wrow[((0 * 3 + dy) * 3 + 2) * 32];
                    fma2(u0ab, wA, p01); fma2(u0ab, wB, p12); fma2(u0ab, wC, p23);
                    fma2(u0cd, wA, p23); fma2(u0cd, wB, p34); fma2(u0cd, wC, p45);
                }
                {
                    unsigned long long wA = wrow[((1 * 3 + dy) * 3 + 0) * 32];
                    unsigned long long wB = wrow[((1 * 3 + dy) * 3 + 1) * 32];
                    unsigned long long wC = wrow[((1 * 3 + dy) * 3 + 2) * 32];
                    fma2(u1ab, wA, p01); fma2(u1ab, wB, p12); fma2(u1ab, wC, p23);
                    fma2(u1cd, wA, p23); fma2(u1cd, wB, p34); fma2(u1cd, wC, p45);
                }
                {
                    unsigned long long wA = wrow[((2 * 3 + dy) * 3 + 0) * 32];
                    unsigned long long wB = wrow[((2 * 3 + dy) * 3 + 1) * 32];
                    unsigned long long wC = wrow[((2 * 3 + dy) * 3 + 2) * 32];
                    fma2(u2ab, wA, p01); fma2(u2ab, wB, p12); fma2(u2ab, wC, p23);
                    fma2(u2cd, wA, p23); fma2(u2cd, wB, p34); fma2(u2cd, wC, p45);
                }
            }
        }
    }

    float2 r0ab = unpack2(u0ab), r0cd = unpack2(u0cd);
    float2 r1ab = unpack2(u1ab), r1cd = unpack2(u1cd);
    float2 r2ab = unpack2(u2ab), r2cd = unpack2(u2cd);

    size_t obase = (((size_t)b * 3 + 0) * DD + d) * plane + (size_t)(h0 + rr) * WW + w0;
    size_t zstep = (size_t)DD * plane;
    *reinterpret_cast<float4*>(g_u + obase)             = make_float4(r0ab.x, r0ab.y, r0cd.x, r0cd.y);
    *reinterpret_cast<float4*>(g_u + obase + zstep)     = make_float4(r1ab.x, r1ab.y, r1cd.x, r1cd.y);
    *reinterpret_cast<float4*>(g_u + obase + 2 * zstep) = make_float4(r2ab.x, r2ab.y, r2cd.x, r2cd.y);
}

// ---------------------------------------------------------------------------
// Final: pre[d] = u0[d-1] + u1[d] + u2[d+1]; softmax over D; expected depth;
// confidence = sum p[idx-1..idx+2]. One block per (b,h) row; stage u in smem.
// ---------------------------------------------------------------------------
__global__ __launch_bounds__(128) void k_final(const float* __restrict__ depthv,
                                               float* __restrict__ out) {
    __shared__ float su[3][DD][WW];   // 48 KB

    const int tid = threadIdx.x;
    const int h = blockIdx.x % HH;
    const int b = blockIdx.x / HH;
    const size_t plane = (size_t)HH * WW;

    #pragma unroll
    for (int i = tid; i < 3 * DD * (WW / 4); i += 128) {
        int zz = i / (DD * (WW / 4));
        int dd = (i / (WW / 4)) % DD;
        int j  = i % (WW / 4);
        const float* src = g_u + (((size_t)b * 3 + zz) * DD + dd) * plane + (size_t)h * WW + j * 4;
        float4 v = *reinterpret_cast<const float4*>(src);
        *reinterpret_cast<float4*>(&su[zz][dd][j * 4]) = v;
    }
    __syncthreads();

    const int w = tid;
    float pre[DD];
    #pragma unroll
    for (int d = 0; d < DD; d++) {
        float v = su[1][d][w];
        if (d > 0)      v += su[0][d - 1][w];
        if (d < DD - 1) v += su[2][d + 1][w];
        pre[d] = v;
    }

    float m = pre[0];
    #pragma unroll
    for (int d = 1; d < DD; d++) m = fmaxf(m, pre[d]);

    float s = 0.f;
    #pragma unroll
    for (int d = 0; d < DD; d++) {
        float e = __expf(pre[d] - m);
        pre[d] = e;
        s += e;
    }
    float inv = 1.0f / s;

    const float* dv = depthv + (size_t)b * DD * plane + (size_t)h * WW + w;
    float depth = 0.f, sidx = 0.f;
    #pragma unroll
    for (int d = 0; d < DD; d++) {
        float p = pre[d] * inv;
        pre[d] = p;
        depth += p * dv[(size_t)d * plane];
        sidx  += p * (float)d;
    }

    int idx = (int)sidx;
    if (idx < 0) idx = 0;
    if (idx > DD - 1) idx = DD - 1;

    float conf = 0.f;
    #pragma unroll
    for (int d = 0; d < DD; d++) {
        if (d >= idx - 1 && d <= idx + 2) conf += pre[d];
    }

    int gid = (b * HH + h) * WW + w;
    out[gid] = depth;
    out[BB * HH * WW + gid] = conf;
}

// ---------------------------------------------------------------------------
extern "C" void kernel_launch(void* const* d_in, const int* in_sizes, int n_in,
                              void* d_out, int out_size) {
    const float* features = (const float*)d_in[0];   // (B,V,C,H,W)
    const float* proj     = (const float*)d_in[1];   // (B,V,2,4,4)
    const float* depthv   = (const float*)d_in[2];   // (B,D,H,W)
    const float* wreg     = (const float*)d_in[3];   // (1,C,3,3,3)
    // d_in[4] = b_reg: cancels in softmax, unused
    float* out = (float*)d_out;

    k_fused<<<BB * NTILE * DD, 256>>>(features, proj, depthv, wreg);
    k_final<<<BB * HH, 128>>>(depthv, out);
}